// round 2
// baseline (speedup 1.0000x reference)
#include <cuda_runtime.h>
#include <cuda_bf16.h>
#include <cstdint>

// Problem constants (from reference):
//   x: [32, 2048] token ids in [0, 100000)  -- int32 on device (JAX x64 disabled)
//   W: [256, 100000] float32  (EMBED-major; gather axis V is strided)
//   b: [256] float32
//   out: [32*2048, 256] float32 = W[:, x[t]] + b
static constexpr int VOCAB  = 100000;
static constexpr int EMBED  = 256;
static constexpr int NTOK   = 32 * 2048;          // 65536 tokens
static constexpr int CHUNKS = EMBED / 4;          // 64 float4 chunks per token

// One thread per (token, chunk-of-4-embed-dims).
// 4 independent strided loads from W (each its own 32B sector -> MLP=4/thread),
// one coalesced float4 store to out.
__global__ __launch_bounds__(256) void embedding_gather_kernel(
    const int*   __restrict__ x,
    const float* __restrict__ W,
    const float* __restrict__ bias,
    float*       __restrict__ out)
{
    const int gid = blockIdx.x * blockDim.x + threadIdx.x;   // token*64 + chunk
    const int token = gid >> 6;
    const int chunk = gid & 63;
    if (token >= NTOK) return;

    int v = __ldg(&x[token]);
    // Fault guard: branch-free clamp. Valid inputs are unchanged; if the dtype
    // assumption were wrong we'd get a value mismatch (diagnosable), not a crash.
    v = min(max(v, 0), VOCAB - 1);

    const int e0 = chunk << 2;
    const float* wp = W + (size_t)e0 * VOCAB + (size_t)v;
    float4 r;
    r.x = __ldg(wp);
    r.y = __ldg(wp + (size_t)VOCAB);
    r.z = __ldg(wp + (size_t)2 * VOCAB);
    r.w = __ldg(wp + (size_t)3 * VOCAB);

    const float4 bb = __ldg(reinterpret_cast<const float4*>(bias) + chunk);
    r.x += bb.x; r.y += bb.y; r.z += bb.z; r.w += bb.w;

    reinterpret_cast<float4*>(out)[gid] = r;
}

extern "C" void kernel_launch(void* const* d_in, const int* in_sizes, int n_in,
                              void* d_out, int out_size)
{
    const int*   x    = (const int*)d_in[0];     // int32 [32,2048]
    const float* W    = (const float*)d_in[1];   // f32 [256,100000]
    const float* bias = (const float*)d_in[2];   // f32 [256]
    float*       out  = (float*)d_out;           // f32 [65536,256]

    const int total_threads = NTOK * CHUNKS;     // 4,194,304
    const int block = 256;
    const int grid  = total_threads / block;     // 16384
    embedding_gather_kernel<<<grid, block>>>(x, W, bias, out);
}

// round 4
// speedup vs baseline: 1.3047x; 1.3047x over previous
#include <cuda_runtime.h>
#include <cuda_bf16.h>
#include <cstdint>

// x: [32,2048] int32 ids in [0,100000); W: [256,100000] f32 (EMBED-major);
// b: [256] f32; out: [65536,256] f32 = W[:, x[t]] + b.
//
// Dim-major CTA schedule: each group of 256 consecutive CTAs handles 8 embed
// dims for ALL 65536 tokens. Resident-CTA window then spans only ~5 dim-groups
// (~14 MB of W) -> W sectors stay L2-resident across their ~5.24 token reuses.
static constexpr int VOCAB = 100000;
static constexpr int EMBED = 256;
static constexpr int NTOK  = 32 * 2048;           // 65536
static constexpr int DPT   = 8;                   // dims per thread
static constexpr int GROUPS = EMBED / DPT;        // 32 dim-groups
static constexpr int CTAS_PER_GROUP = NTOK / 256; // 256 CTAs per group

__global__ __launch_bounds__(256) void embedding_gather_dimmajor(
    const int*   __restrict__ x,
    const float* __restrict__ W,
    const float* __restrict__ bias,
    float*       __restrict__ out)
{
    const int group = blockIdx.x >> 8;                       // 0..31
    const int token = ((blockIdx.x & 255) << 8) + threadIdx.x; // 0..65535

    int v = __ldg(&x[token]);
    v = min(max(v, 0), VOCAB - 1);   // fault guard; no-op for valid input

    const int e0 = group << 3;       // first of 8 consecutive dims
    const float* wp = W + (size_t)e0 * VOCAB + (size_t)v;

    float r[DPT];
#pragma unroll
    for (int i = 0; i < DPT; ++i)
        r[i] = __ldg(wp + (size_t)i * VOCAB);   // 8 independent 32B-sector loads

    const float4 b0 = __ldg(reinterpret_cast<const float4*>(bias) + 2 * group);
    const float4 b1 = __ldg(reinterpret_cast<const float4*>(bias) + 2 * group + 1);

    float4 o0 = make_float4(r[0] + b0.x, r[1] + b0.y, r[2] + b0.z, r[3] + b0.w);
    float4 o1 = make_float4(r[4] + b1.x, r[5] + b1.y, r[6] + b1.z, r[7] + b1.w);

    // out row = token*256 floats; dims [e0, e0+8) -> 32 contiguous bytes
    float4* op = reinterpret_cast<float4*>(out) + (size_t)token * (EMBED / 4) + 2 * group;
    op[0] = o0;
    op[1] = o1;
}

extern "C" void kernel_launch(void* const* d_in, const int* in_sizes, int n_in,
                              void* d_out, int out_size)
{
    const int*   x    = (const int*)d_in[0];
    const float* W    = (const float*)d_in[1];
    const float* bias = (const float*)d_in[2];
    float*       out  = (float*)d_out;

    const int grid = GROUPS * CTAS_PER_GROUP;   // 8192
    embedding_gather_dimmajor<<<grid, 256>>>(x, W, bias, out);
}

// round 5
// speedup vs baseline: 1.7000x; 1.3029x over previous
#include <cuda_runtime.h>
#include <cuda_bf16.h>
#include <cstdint>

// x: [32,2048] int32 ids in [0,100000); W: [256,100000] f32 (EMBED-major);
// b: [256] f32; out: [65536,256] f32 = W[:, x[t]] + b.
//
// Strategy: bucket-sort tokens by (id>>5) so warp lanes hit the same 128B
// W-lines (avg 21 tokens/line) -> HW-coalesced gather; smem tile transpose
// so out rows are written fully contiguously (row-granular scatter).
static constexpr int VOCAB = 100000;
static constexpr int EMBED = 256;
static constexpr int NTOK  = 32 * 2048;            // 65536
static constexpr int NBINS = (VOCAB + 31) / 32;    // 3125 line-buckets

__device__ int g_bins[NBINS];
__device__ int g_offs[NBINS];
__device__ int g_sorted_id[NTOK];
__device__ int g_sorted_tok[NTOK];

__device__ __forceinline__ int clamp_id(int v) {
    return min(max(v, 0), VOCAB - 1);
}

// ---- K0: zero bins -------------------------------------------------------
__global__ void zero_kernel() {
    int i = blockIdx.x * 256 + threadIdx.x;
    if (i < NBINS) g_bins[i] = 0;
}

// ---- K1: histogram over line-buckets ------------------------------------
__global__ __launch_bounds__(256) void hist_kernel(const int* __restrict__ x) {
    int t = blockIdx.x * 256 + threadIdx.x;          // 0..65535
    int v = clamp_id(__ldg(&x[t]));
    atomicAdd(&g_bins[v >> 5], 1);
}

// ---- K2: single-CTA exclusive scan of 3125 bins -> g_offs ---------------
__global__ __launch_bounds__(1024) void scan_kernel() {
    __shared__ int partial[1024];
    const int tid = threadIdx.x;
    int local[4];
    int s = 0;
#pragma unroll
    for (int k = 0; k < 4; ++k) {                    // bins tid*4 .. tid*4+3
        int idx = tid * 4 + k;
        int c = (idx < NBINS) ? g_bins[idx] : 0;
        local[k] = s; s += c;
    }
    partial[tid] = s;
    __syncthreads();
    for (int off = 1; off < 1024; off <<= 1) {       // Hillis-Steele inclusive
        int v = (tid >= off) ? partial[tid - off] : 0;
        __syncthreads();
        partial[tid] += v;
        __syncthreads();
    }
    int base = (tid > 0) ? partial[tid - 1] : 0;
#pragma unroll
    for (int k = 0; k < 4; ++k) {
        int idx = tid * 4 + k;
        if (idx < NBINS) g_offs[idx] = base + local[k];
    }
}

// ---- K3: scatter tokens into bucket-sorted order ------------------------
__global__ __launch_bounds__(256) void scatter_kernel(const int* __restrict__ x) {
    int t = blockIdx.x * 256 + threadIdx.x;
    int v = clamp_id(__ldg(&x[t]));
    int pos = atomicAdd(&g_offs[v >> 5], 1);
    g_sorted_id[pos]  = v;
    g_sorted_tok[pos] = t;
}

// ---- K4: coalesced gather + smem transpose + contiguous row writes ------
// CTA = 256 threads handles 32 sorted tokens x all 256 dims.
// Load:  warp w covers dims [32w,32w+32); lane l loads W[e][id_l] -> ids are
//        sorted so lanes cluster into ~2-3 lines per LDG (HW coalesced).
// Write: warp w writes tokens 4w..4w+3; lanes cover 32 consecutive dims
//        -> fully coalesced 128B stores into the token's out row.
__global__ __launch_bounds__(256) void gather_kernel(
    const float* __restrict__ W,
    const float* __restrict__ bias,
    float*       __restrict__ out)
{
    __shared__ float tile[EMBED][33];   // [dim][token], pad 33 -> conflict-free
    __shared__ int s_id[32], s_tok[32];

    const int tid  = threadIdx.x;
    const int base = blockIdx.x * 32;
    if (tid < 32) {
        s_id[tid]  = g_sorted_id[base + tid];
        s_tok[tid] = g_sorted_tok[base + tid];
    }
    __syncthreads();

    const int w = tid >> 5;
    const int l = tid & 31;

    // load phase: 32 independent strided LDGs per lane (MLP high), then STS
    const int vid = s_id[l];
    const float* wp = W + (size_t)(w * 32) * VOCAB + (size_t)vid;
    float rr[32];
#pragma unroll
    for (int j = 0; j < 32; ++j)
        rr[j] = __ldg(wp + (size_t)j * VOCAB);
#pragma unroll
    for (int j = 0; j < 32; ++j)
        tile[w * 32 + j][l] = rr[j];                 // banks (e+l)%32: clean
    __syncthreads();

    // bias: lane l needs dims l, l+32, ..., l+224
    float bv[8];
#pragma unroll
    for (int k = 0; k < 8; ++k) bv[k] = __ldg(bias + l + 32 * k);

    // write phase
#pragma unroll
    for (int i = 0; i < 4; ++i) {
        const int t    = w * 4 + i;
        const int orig = s_tok[t];
        float* op = out + (size_t)orig * EMBED;
#pragma unroll
        for (int k = 0; k < 8; ++k)
            op[l + 32 * k] = tile[l + 32 * k][t] + bv[k];  // LDS banks (l+t)%32: clean
    }
}

extern "C" void kernel_launch(void* const* d_in, const int* in_sizes, int n_in,
                              void* d_out, int out_size)
{
    const int*   x    = (const int*)d_in[0];
    const float* W    = (const float*)d_in[1];
    const float* bias = (const float*)d_in[2];
    float*       out  = (float*)d_out;

    zero_kernel<<<(NBINS + 255) / 256, 256>>>();
    hist_kernel<<<NTOK / 256, 256>>>(x);
    scan_kernel<<<1, 1024>>>();
    scatter_kernel<<<NTOK / 256, 256>>>(x);
    gather_kernel<<<NTOK / 32, 256>>>(W, bias, out);
}

// round 6
// speedup vs baseline: 2.0126x; 1.1839x over previous
#include <cuda_runtime.h>
#include <cuda_bf16.h>
#include <cstdint>

// x: [32,2048] int32 ids in [0,100000); W: [256,100000] f32 (EMBED-major);
// b: [256] f32; out: [65536,256] f32 = W[:, x[t]] + b.
//
// Pipeline (4 launches):
//  K1 hist_rank : rank[t] = atomicAdd(bins[id>>5], 1)
//  K2 scan      : offs = exclusive_scan(bins); bins = 0  (invariant restore)
//  K3 scatter   : sorted[offs[bin]+rank[t]] = {id, t}    (atomic-free)
//  K4 gather    : warp-coalesced W gather + smem transpose + contiguous
//                 row writes with evict-first stores (preserve W in L2
//                 across graph replays; L2 is not flushed per launch).
static constexpr int VOCAB = 100000;
static constexpr int EMBED = 256;
static constexpr int NTOK  = 32 * 2048;            // 65536
static constexpr int NBINS = (VOCAB + 31) / 32;    // 3125 line-buckets

__device__ int  g_bins[NBINS];     // zero at load; scan re-zeroes each launch
__device__ int  g_offs[NBINS];
__device__ int  g_rank[NTOK];
__device__ int2 g_sorted[NTOK];    // {id, token}

__device__ __forceinline__ int clamp_id(int v) {
    return min(max(v, 0), VOCAB - 1);
}

// ---- K1: histogram + per-token rank within bin --------------------------
__global__ __launch_bounds__(256) void hist_rank_kernel(const int* __restrict__ x) {
    int t = blockIdx.x * 256 + threadIdx.x;          // 0..65535
    int v = clamp_id(__ldg(&x[t]));
    g_rank[t] = atomicAdd(&g_bins[v >> 5], 1);
}

// ---- K2: single-CTA exclusive scan of 3125 bins; consume-and-zero -------
__global__ __launch_bounds__(1024) void scan_kernel() {
    __shared__ int partial[1024];
    const int tid = threadIdx.x;
    int local[4];
    int s = 0;
#pragma unroll
    for (int k = 0; k < 4; ++k) {                    // bins tid*4 .. tid*4+3
        int idx = tid * 4 + k;
        int c = (idx < NBINS) ? g_bins[idx] : 0;
        if (idx < NBINS) g_bins[idx] = 0;            // restore invariant
        local[k] = s; s += c;
    }
    partial[tid] = s;
    __syncthreads();
    for (int off = 1; off < 1024; off <<= 1) {       // Hillis-Steele inclusive
        int v = (tid >= off) ? partial[tid - off] : 0;
        __syncthreads();
        partial[tid] += v;
        __syncthreads();
    }
    int base = (tid > 0) ? partial[tid - 1] : 0;
#pragma unroll
    for (int k = 0; k < 4; ++k) {
        int idx = tid * 4 + k;
        if (idx < NBINS) g_offs[idx] = base + local[k];
    }
}

// ---- K3: atomic-free scatter into bucket-sorted order -------------------
__global__ __launch_bounds__(256) void scatter_kernel(const int* __restrict__ x) {
    int t = blockIdx.x * 256 + threadIdx.x;
    int v = clamp_id(__ldg(&x[t]));
    int pos = __ldg(&g_offs[v >> 5]) + g_rank[t];
    g_sorted[pos] = make_int2(v, t);
}

// ---- K4: coalesced gather + smem transpose + contiguous row writes ------
// CTA = 256 threads handles 32 sorted tokens x all 256 dims.
// Load:  warp w covers dims [32w,32w+32); lanes hold 32 sorted ids ->
//        ~2-3 distinct 128B lines per LDG (HW coalesced).
// Write: warp w writes tokens 4w..4w+3, full contiguous rows, evict-first.
__global__ __launch_bounds__(256) void gather_kernel(
    const float* __restrict__ W,
    const float* __restrict__ bias,
    float*       __restrict__ out)
{
    __shared__ float tile[EMBED][33];   // [dim][token], pad -> conflict-free
    __shared__ int s_id[32], s_tok[32];

    const int tid  = threadIdx.x;
    const int base = blockIdx.x * 32;
    if (tid < 32) {
        int2 p = g_sorted[base + tid];
        s_id[tid]  = p.x;
        s_tok[tid] = p.y;
    }
    __syncthreads();

    const int w = tid >> 5;
    const int l = tid & 31;

    const int vid = s_id[l];
    const float* wp = W + (size_t)(w * 32) * VOCAB + (size_t)vid;
    float rr[32];
#pragma unroll
    for (int j = 0; j < 32; ++j)
        rr[j] = __ldg(wp + (size_t)j * VOCAB);       // 32 independent loads
#pragma unroll
    for (int j = 0; j < 32; ++j)
        tile[w * 32 + j][l] = rr[j];
    __syncthreads();

    float bv[8];
#pragma unroll
    for (int k = 0; k < 8; ++k) bv[k] = __ldg(bias + l + 32 * k);

#pragma unroll
    for (int i = 0; i < 4; ++i) {
        const int t    = w * 4 + i;
        const int orig = s_tok[t];
        float* op = out + (size_t)orig * EMBED;
#pragma unroll
        for (int k = 0; k < 8; ++k)
            __stcs(op + l + 32 * k, tile[l + 32 * k][t] + bv[k]); // evict-first
    }
}

extern "C" void kernel_launch(void* const* d_in, const int* in_sizes, int n_in,
                              void* d_out, int out_size)
{
    const int*   x    = (const int*)d_in[0];
    const float* W    = (const float*)d_in[1];
    const float* bias = (const float*)d_in[2];
    float*       out  = (float*)d_out;

    hist_rank_kernel<<<NTOK / 256, 256>>>(x);
    scan_kernel<<<1, 1024>>>();
    scatter_kernel<<<NTOK / 256, 256>>>(x);
    gather_kernel<<<NTOK / 32, 256>>>(W, bias, out);
}

// round 7
// speedup vs baseline: 2.7683x; 1.3755x over previous
#include <cuda_runtime.h>
#include <cuda_bf16.h>
#include <cstdint>

// x: [32,2048] int32 ids in [0,100000); W: [256,100000] f32 (EMBED-major);
// b: [256] f32; out: [65536,256] f32 = W[:, x[t]] + b.
//
// K1 hist_rank : rank[t] = atomicAdd(bins[id>>5], 1)
// K2 scan      : offs = exclusive_scan(bins); bins = 0 (invariant restore)
// K3 scatter   : sorted[offs[bin]+rank[t]] = {id, t}   (atomic-free)
// K4 gather    : CTA = 32 sorted tokens x 128 dims (half-row). Coalesced
//                strided LDGs -> STS.128 into [token][dim] tile (stride 132:
//                = 4 mod 32 -> phase-conflict-free for .128 ops) ->
//                LDS.128 + bias + STG.128 full contiguous quarter-rows.
static constexpr int VOCAB = 100000;
static constexpr int EMBED = 256;
static constexpr int NTOK  = 32 * 2048;            // 65536
static constexpr int NBINS = (VOCAB + 31) / 32;    // 3125 line-buckets
static constexpr int HDIM  = 128;                  // dims per gather CTA
static constexpr int TSTR  = 132;                  // tile stride (floats)

__device__ int  g_bins[NBINS];     // zero at load; scan re-zeroes each launch
__device__ int  g_offs[NBINS];
__device__ int  g_rank[NTOK];
__device__ int2 g_sorted[NTOK];    // {id, token}

__device__ __forceinline__ int clamp_id(int v) {
    return min(max(v, 0), VOCAB - 1);
}

// ---- K1: histogram + per-token rank within bin --------------------------
__global__ __launch_bounds__(256) void hist_rank_kernel(const int* __restrict__ x) {
    int t = blockIdx.x * 256 + threadIdx.x;
    int v = clamp_id(__ldg(&x[t]));
    g_rank[t] = atomicAdd(&g_bins[v >> 5], 1);
}

// ---- K2: single-CTA exclusive scan of 3125 bins; consume-and-zero -------
__global__ __launch_bounds__(1024) void scan_kernel() {
    __shared__ int partial[1024];
    const int tid = threadIdx.x;
    int local[4];
    int s = 0;
#pragma unroll
    for (int k = 0; k < 4; ++k) {
        int idx = tid * 4 + k;
        int c = (idx < NBINS) ? g_bins[idx] : 0;
        if (idx < NBINS) g_bins[idx] = 0;            // restore invariant
        local[k] = s; s += c;
    }
    partial[tid] = s;
    __syncthreads();
    for (int off = 1; off < 1024; off <<= 1) {
        int v = (tid >= off) ? partial[tid - off] : 0;
        __syncthreads();
        partial[tid] += v;
        __syncthreads();
    }
    int base = (tid > 0) ? partial[tid - 1] : 0;
#pragma unroll
    for (int k = 0; k < 4; ++k) {
        int idx = tid * 4 + k;
        if (idx < NBINS) g_offs[idx] = base + local[k];
    }
}

// ---- K3: atomic-free scatter into bucket-sorted order -------------------
__global__ __launch_bounds__(256) void scatter_kernel(const int* __restrict__ x) {
    int t = blockIdx.x * 256 + threadIdx.x;
    int v = clamp_id(__ldg(&x[t]));
    int pos = __ldg(&g_offs[v >> 5]) + g_rank[t];
    g_sorted[pos] = make_int2(v, t);
}

// ---- K4: gather, 32 tokens x 128 dims per CTA ---------------------------
// blockIdx: bit0 = dim half, bits[1..] = token group (halves adjacent for
// L2 temporal locality on the sorted-token window).
__global__ __launch_bounds__(256) void gather_kernel(
    const float* __restrict__ W,
    const float* __restrict__ bias,
    float*       __restrict__ out)
{
    __shared__ __align__(16) float tile[32][TSTR];   // [token][dim], stride 132
    __shared__ int s_id[32], s_tok[32];

    const int tid   = threadIdx.x;
    const int group = blockIdx.x >> 1;
    const int half  = blockIdx.x & 1;
    const int base  = group * 32;
    const int dim0  = half * HDIM;

    if (tid < 32) {
        int2 p = g_sorted[base + tid];
        s_id[tid]  = p.x;
        s_tok[tid] = p.y;
    }
    __syncthreads();

    const int w = tid >> 5;          // warp 0..7 -> dims [16w, 16w+16)
    const int l = tid & 31;          // lane -> sorted token

    // Load: 16 independent strided LDGs; lanes hold sorted ids -> HW-coalesced.
    const int vid = s_id[l];
    const float* wp = W + (size_t)(dim0 + w * 16) * VOCAB + (size_t)vid;
    float rr[16];
#pragma unroll
    for (int j = 0; j < 16; ++j)
        rr[j] = __ldg(wp + (size_t)j * VOCAB);

    // STS.128 x4: contiguous dims of token l.
#pragma unroll
    for (int j = 0; j < 4; ++j) {
        float4 v4 = make_float4(rr[4*j], rr[4*j+1], rr[4*j+2], rr[4*j+3]);
        *reinterpret_cast<float4*>(&tile[l][w * 16 + 4 * j]) = v4;
    }
    __syncthreads();

    // Bias: lane l covers dims dim0 + 4l .. +3
    const float4 bv = __ldg(reinterpret_cast<const float4*>(bias) + half * 32 + l);

    // Write: warp w -> tokens 4w..4w+3; lane l -> float4 at dim offset 4l.
#pragma unroll
    for (int i = 0; i < 4; ++i) {
        const int t    = w * 4 + i;
        const int orig = s_tok[t];
        float4 v4 = *reinterpret_cast<const float4*>(&tile[t][4 * l]);
        v4.x += bv.x; v4.y += bv.y; v4.z += bv.z; v4.w += bv.w;
        __stcs(reinterpret_cast<float4*>(out + (size_t)orig * EMBED + dim0) + l, v4);
    }
}

extern "C" void kernel_launch(void* const* d_in, const int* in_sizes, int n_in,
                              void* d_out, int out_size)
{
    const int*   x    = (const int*)d_in[0];
    const float* W    = (const float*)d_in[1];
    const float* bias = (const float*)d_in[2];
    float*       out  = (float*)d_out;

    hist_rank_kernel<<<NTOK / 256, 256>>>(x);
    scan_kernel<<<1, 1024>>>();
    scatter_kernel<<<NTOK / 256, 256>>>(x);
    gather_kernel<<<(NTOK / 32) * 2, 256>>>(W, bias, out);
}